// round 7
// baseline (speedup 1.0000x reference)
#include <cuda_runtime.h>

#define Z 64      // z_dim
#define H 256     // hidden
#define C 5       // num classes
#define GMAX 16
#define MAXBLK 64

// partial class sums: layout [g][c][blk][d]
__device__ __align__(16) float g_part[GMAX * C * MAXBLK * Z];
__device__ int      g_cntp[GMAX * MAXBLK * C];   // per (g, chunk) class counts
__device__ __align__(16) float g_D[GMAX * C * Z];
__device__ unsigned          g_arrive[GMAX];
__device__ volatile unsigned g_flag[GMAX];
__device__ unsigned          g_done[GMAX];

__device__ __forceinline__ void acc_add(float4& a, const float4& v) {
    a.x += v.x; a.y += v.y; a.z += v.z; a.w += v.w;
}

// Persistent fused kernel, per-graph decoupled sync. Grid (nblk, G), single
// wave (nblk*G <= 592 @ 4/SM, required for the spin loops to be safe).
__global__ void __launch_bounds__(256, 4)
fused_kernel(const float* __restrict__ x,
             const int*   __restrict__ label,
             const float* __restrict__ W1,
             const float* __restrict__ b1,
             const float* __restrict__ W2,
             const float* __restrict__ b2,
             float*       __restrict__ out,
             int N, int chunk, int nblk) {
    int g   = blockIdx.y;
    int bx  = blockIdx.x;
    int tid = threadIdx.x;
    int n0  = bx * chunk;
    int n1  = min(n0 + chunk, N);

    __shared__ float4 sacc[16][C][16];     // 20 KB
    __shared__ float  s_mid[Z];
    __shared__ float  h_mid[H];
    __shared__ float  part[4][Z];
    __shared__ int    scnt[C];
    __shared__ int    s_exec;
    __shared__ float4 sD[C * 16];

    // ---------------- phase 1a: count labels of own chunk -----------------
    {
        int cnt[C];
#pragma unroll
        for (int c = 0; c < C; c++) cnt[c] = 0;
        for (int n = n0 + tid; n < n1; n += 256) {
            int c = __ldg(label + n);
#pragma unroll
            for (int cc = 0; cc < C; cc++) cnt[cc] += (cc == c);
        }
        if (tid < C) scnt[tid] = 0;
        __syncthreads();
#pragma unroll
        for (int cc = 0; cc < C; cc++)
            if (cnt[cc]) atomicAdd(&scnt[cc], cnt[cc]);
        __syncthreads();
        if (tid < C) g_cntp[(g * nblk + bx) * C + tid] = scnt[tid];
    }

    // ---------------- phase 1b: per-class sum of own chunk ----------------
    {
        int lane = tid & 15;   // float4 index within 64-dim row
        int grp  = tid >> 4;   // 16 node-groups

        float4 acc[C];
#pragma unroll
        for (int c = 0; c < C; c++) acc[c] = make_float4(0.f, 0.f, 0.f, 0.f);

        const float4* x4 = reinterpret_cast<const float4*>(x) + (size_t)g * N * 16;

        int span  = n1 - n0;
        int nEnd6 = n0 + (span - span % 96);
        int n = n0 + grp;
        for (; n < nEnd6; n += 96) {
            int    c0 = __ldg(label + n);
            int    c1 = __ldg(label + n + 16);
            int    c2 = __ldg(label + n + 32);
            int    c3 = __ldg(label + n + 48);
            int    c4 = __ldg(label + n + 64);
            int    c5 = __ldg(label + n + 80);
            float4 v0 = __ldg(x4 + (size_t)n * 16 + lane);
            float4 v1 = __ldg(x4 + (size_t)(n + 16) * 16 + lane);
            float4 v2 = __ldg(x4 + (size_t)(n + 32) * 16 + lane);
            float4 v3 = __ldg(x4 + (size_t)(n + 48) * 16 + lane);
            float4 v4 = __ldg(x4 + (size_t)(n + 64) * 16 + lane);
            float4 v5 = __ldg(x4 + (size_t)(n + 80) * 16 + lane);
#pragma unroll
            for (int cc = 0; cc < C; cc++) {
                if (c0 == cc) acc_add(acc[cc], v0);
                if (c1 == cc) acc_add(acc[cc], v1);
                if (c2 == cc) acc_add(acc[cc], v2);
                if (c3 == cc) acc_add(acc[cc], v3);
                if (c4 == cc) acc_add(acc[cc], v4);
                if (c5 == cc) acc_add(acc[cc], v5);
            }
        }
        for (; n < n1; n += 16) {
            int    c0 = __ldg(label + n);
            float4 v0 = __ldg(x4 + (size_t)n * 16 + lane);
#pragma unroll
            for (int cc = 0; cc < C; cc++)
                if (c0 == cc) acc_add(acc[cc], v0);
        }

#pragma unroll
        for (int c = 0; c < C; c++) sacc[grp][c][lane] = acc[c];
        __syncthreads();

        if (tid < C * 16) {
            int c = tid >> 4, d4 = tid & 15;
            float4 s = sacc[0][c][d4];
#pragma unroll
            for (int g2 = 1; g2 < 16; g2++) {
                float4 t = sacc[g2][c][d4];
                s.x += t.x; s.y += t.y; s.z += t.z; s.w += t.w;
            }
            float4* P4 = reinterpret_cast<float4*>(g_part);
            P4[((size_t)(g * C + c) * nblk + bx) * 16 + d4] = s;
        }
    }

    // ---------------- per-graph arrival; last arriver runs the mid GEMM ---
    __syncthreads();
    if (tid == 0) {
        __threadfence();
        unsigned prev = atomicAdd(&g_arrive[g], 1u);
        s_exec = (prev == (unsigned)(nblk - 1));
    }
    __syncthreads();

    if (s_exec) {
        __threadfence();   // acquire: partials of all graph-g blocks

        // total class counts for this graph's row
        if (tid < C) {
            int sum = 0;
            for (int b = 0; b < nblk; b++)
                sum += g_cntp[(g * nblk + b) * C + tid];
            scnt[tid] = max(sum, 1);
        }
        __syncthreads();

        for (int c = 0; c < C; c++) {
            int r = g * C + c;

            // sum partials (independent loads -> high MLP)
            const float* P = g_part + (size_t)r * nblk * Z;
            int d = tid & 63, j = tid >> 6;
            float p0 = 0.f, p1 = 0.f;
            int b = j;
            for (; b + 4 < nblk; b += 8) {
                p0 += P[b * Z + d];
                p1 += P[(b + 4) * Z + d];
            }
            if (b < nblk) p0 += P[b * Z + d];
            part[j][d] = p0 + p1;
            __syncthreads();

            float inv = 1.f / (float)scnt[c];
            if (tid < Z)
                s_mid[tid] = (part[0][tid] + part[1][tid]
                            + part[2][tid] + part[3][tid]) * inv;
            __syncthreads();

            // layer 1: h[j] = relu(s . W1[:,j] + b1[j])
            float acc = __ldg(b1 + tid);
#pragma unroll
            for (int dd = 0; dd < Z; dd++)
                acc = fmaf(s_mid[dd], __ldg(W1 + dd * H + tid), acc);
            h_mid[tid] = fmaxf(acc, 0.f);
            __syncthreads();

            // layer 2: D[k] = h . W2[:,k] + b2[k]
            int lane = tid & 63, grp = tid >> 6;
            float p2 = 0.f;
#pragma unroll
            for (int jj = 0; jj < 64; jj++) {
                int jidx = grp * 64 + jj;
                p2 = fmaf(h_mid[jidx], __ldg(W2 + jidx * Z + lane), p2);
            }
            __syncthreads();
            part[grp][lane] = p2;
            __syncthreads();
            if (tid < Z)
                g_D[r * Z + tid] = __ldg(b2 + tid) + part[0][tid] + part[1][tid]
                                 + part[2][tid] + part[3][tid];
            __syncthreads();
        }

        if (tid == 0) {
            __threadfence();
            g_flag[g] = 1u;
        }
    }

    // ---------------- wait for this graph's D ----------------------------
    if (tid == 0) {
        while (g_flag[g] == 0u) __nanosleep(64);
        __threadfence();   // acquire: g_D[g]
    }
    __syncthreads();

    if (tid < C * 16)
        sD[tid] = reinterpret_cast<const float4*>(g_D)[g * C * 16 + tid];
    __syncthreads();

    // ---------------- phase 3: out = x + D[label], backward walk ----------
    {
        int lane = tid & 15;
        int grp  = tid >> 4;
        int span = n1 - n0;
        int spanA = span & ~15;

        const float4* x4 = reinterpret_cast<const float4*>(x);
        float4*       o4 = reinterpret_cast<float4*>(out);

        if (grp < (span & 15)) {
            int n = n0 + spanA + grp;
            int    c   = __ldg(label + n);
            size_t idx = ((size_t)g * N + n) * 16 + lane;
            float4 xv  = __ldg(x4 + idx);
            float4 dv  = sD[c * 16 + lane];
            float4 rv;
            rv.x = xv.x + dv.x; rv.y = xv.y + dv.y;
            rv.z = xv.z + dv.z; rv.w = xv.w + dv.w;
            __stcs(o4 + idx, rv);
        }

#pragma unroll 4
        for (int base = spanA - 16; base >= 0; base -= 16) {
            int n = n0 + base + grp;
            int    c   = __ldg(label + n);
            size_t idx = ((size_t)g * N + n) * 16 + lane;
            float4 xv  = __ldg(x4 + idx);
            float4 dv  = sD[c * 16 + lane];
            float4 rv;
            rv.x = xv.x + dv.x; rv.y = xv.y + dv.y;
            rv.z = xv.z + dv.z; rv.w = xv.w + dv.w;
            __stcs(o4 + idx, rv);
        }
    }

    // ---------------- self-reset for graph replay -------------------------
    __syncthreads();
    if (tid == 0) {
        __threadfence();
        unsigned prev = atomicAdd(&g_done[g], 1u);
        if (prev == (unsigned)(nblk - 1)) {
            g_arrive[g] = 0u;
            g_flag[g]   = 0u;
            g_done[g]   = 0u;
            __threadfence();
        }
    }
}

// ---------------------------------------------------------------- launcher
extern "C" void kernel_launch(void* const* d_in, const int* in_sizes, int n_in,
                              void* d_out, int out_size) {
    const float* x     = (const float*)d_in[0];
    const int*   label = (const int*)  d_in[1];
    const float* W1    = (const float*)d_in[2];
    const float* b1    = (const float*)d_in[3];
    const float* W2    = (const float*)d_in[4];
    const float* b2    = (const float*)d_in[5];
    float*       out   = (float*)d_out;

    int N = in_sizes[1];                 // 40000
    int G = in_sizes[0] / (N * Z);       // 16

    // Single wave: blocks = G * nblk <= 576 (< 592 slots @ 4/SM).
    int nblk = 576 / G;                  // 36 for G=16
    if (nblk > MAXBLK) nblk = MAXBLK;
    int chunk = ((N + nblk - 1) / nblk + 15) & ~15;   // multiple of 16
    nblk = (N + chunk - 1) / chunk;

    dim3 grid(nblk, G);
    fused_kernel<<<grid, 256>>>(x, label, W1, b1, W2, b2, out, N, chunk, nblk);
}

// round 8
// speedup vs baseline: 1.1061x; 1.1061x over previous
#include <cuda_runtime.h>

#define Z 64      // z_dim
#define H 256     // hidden
#define C 5       // num classes
#define GMAX 16
#define MAXBLK 64

// partial class sums: layout [g][c][blk][d]
__device__ __align__(16) float g_part[GMAX * C * MAXBLK * Z];
__device__ int      g_cntp[GMAX * MAXBLK * C];   // per (g, chunk) class counts
__device__ __align__(16) float g_D[GMAX * C * Z];
__device__ unsigned          g_arrive[GMAX];
__device__ volatile unsigned g_ready[GMAX];
__device__ unsigned          g_done[GMAX];

__device__ __forceinline__ void acc_add(float4& a, const float4& v) {
    a.x += v.x; a.y += v.y; a.z += v.z; a.w += v.w;
}

// Persistent fused kernel, per-graph decoupled sync, PARALLEL mid (5 blocks
// per graph). Grid (nblk, G), single wave (nblk*G <= 592 @ 4/SM — required
// for the spin loops to be deadlock-free).
__global__ void __launch_bounds__(256, 4)
fused_kernel(const float* __restrict__ x,
             const int*   __restrict__ label,
             const float* __restrict__ W1,
             const float* __restrict__ b1,
             const float* __restrict__ W2,
             const float* __restrict__ b2,
             float*       __restrict__ out,
             int N, int chunk, int nblk) {
    int g   = blockIdx.y;
    int bx  = blockIdx.x;
    int tid = threadIdx.x;
    int n0  = bx * chunk;
    int n1  = min(n0 + chunk, N);

    __shared__ float4 sacc[16][C][16];     // 20 KB
    __shared__ float  s_mid[Z];
    __shared__ float  h_mid[H];
    __shared__ float  part[4][Z];
    __shared__ int    scnt[C];
    __shared__ float4 sD[C * 16];

    // ---------------- phase 1a: count labels of own chunk -----------------
    {
        int cnt[C];
#pragma unroll
        for (int c = 0; c < C; c++) cnt[c] = 0;
        for (int n = n0 + tid; n < n1; n += 256) {
            int c = __ldg(label + n);
#pragma unroll
            for (int cc = 0; cc < C; cc++) cnt[cc] += (cc == c);
        }
        if (tid < C) scnt[tid] = 0;
        __syncthreads();
#pragma unroll
        for (int cc = 0; cc < C; cc++)
            if (cnt[cc]) atomicAdd(&scnt[cc], cnt[cc]);
        __syncthreads();
        if (tid < C) g_cntp[(g * nblk + bx) * C + tid] = scnt[tid];
    }

    // ---------------- phase 1b: per-class sum of own chunk ----------------
    {
        int lane = tid & 15;   // float4 index within 64-dim row
        int grp  = tid >> 4;   // 16 node-groups

        float4 acc[C];
#pragma unroll
        for (int c = 0; c < C; c++) acc[c] = make_float4(0.f, 0.f, 0.f, 0.f);

        const float4* x4 = reinterpret_cast<const float4*>(x) + (size_t)g * N * 16;

        int span  = n1 - n0;
        int nEnd6 = n0 + (span - span % 96);
        int n = n0 + grp;
        for (; n < nEnd6; n += 96) {
            int    c0 = __ldg(label + n);
            int    c1 = __ldg(label + n + 16);
            int    c2 = __ldg(label + n + 32);
            int    c3 = __ldg(label + n + 48);
            int    c4 = __ldg(label + n + 64);
            int    c5 = __ldg(label + n + 80);
            float4 v0 = __ldg(x4 + (size_t)n * 16 + lane);
            float4 v1 = __ldg(x4 + (size_t)(n + 16) * 16 + lane);
            float4 v2 = __ldg(x4 + (size_t)(n + 32) * 16 + lane);
            float4 v3 = __ldg(x4 + (size_t)(n + 48) * 16 + lane);
            float4 v4 = __ldg(x4 + (size_t)(n + 64) * 16 + lane);
            float4 v5 = __ldg(x4 + (size_t)(n + 80) * 16 + lane);
#pragma unroll
            for (int cc = 0; cc < C; cc++) {
                if (c0 == cc) acc_add(acc[cc], v0);
                if (c1 == cc) acc_add(acc[cc], v1);
                if (c2 == cc) acc_add(acc[cc], v2);
                if (c3 == cc) acc_add(acc[cc], v3);
                if (c4 == cc) acc_add(acc[cc], v4);
                if (c5 == cc) acc_add(acc[cc], v5);
            }
        }
        for (; n < n1; n += 16) {
            int    c0 = __ldg(label + n);
            float4 v0 = __ldg(x4 + (size_t)n * 16 + lane);
#pragma unroll
            for (int cc = 0; cc < C; cc++)
                if (c0 == cc) acc_add(acc[cc], v0);
        }

#pragma unroll
        for (int c = 0; c < C; c++) sacc[grp][c][lane] = acc[c];
        __syncthreads();

        if (tid < C * 16) {
            int c = tid >> 4, d4 = tid & 15;
            float4 s = sacc[0][c][d4];
#pragma unroll
            for (int g2 = 1; g2 < 16; g2++) {
                float4 t = sacc[g2][c][d4];
                s.x += t.x; s.y += t.y; s.z += t.z; s.w += t.w;
            }
            float4* P4 = reinterpret_cast<float4*>(g_part);
            P4[((size_t)(g * C + c) * nblk + bx) * 16 + d4] = s;
        }
    }

    // ---------------- per-graph arrival -----------------------------------
    __syncthreads();
    if (tid == 0) {
        __threadfence();
        atomicAdd(&g_arrive[g], 1u);
    }
    __syncthreads();

    // ---------------- phase 2: parallel mid GEMM (blocks bx < C) ----------
    if (bx < C) {
        int c = bx;
        int r = g * C + c;

        // wait until all blocks of this graph have flushed their partials
        if (tid == 0) {
            while (*(volatile unsigned*)&g_arrive[g] < (unsigned)nblk)
                __nanosleep(64);
            __threadfence();   // acquire
        }
        __syncthreads();

        // total class count for (g, c)
        if (tid < 32) {
            int sum = 0;
            for (int b = tid; b < nblk; b += 32)
                sum += g_cntp[(g * nblk + b) * C + c];
#pragma unroll
            for (int o = 16; o > 0; o >>= 1)
                sum += __shfl_down_sync(0xffffffffu, sum, o);
            if (tid == 0) scnt[0] = max(sum, 1);
        }

        // sum partials (independent loads -> high MLP)
        const float* P = g_part + (size_t)r * nblk * Z;
        int d = tid & 63, j = tid >> 6;
        float p0 = 0.f, p1 = 0.f;
        int b = j;
        for (; b + 4 < nblk; b += 8) {
            p0 += P[b * Z + d];
            p1 += P[(b + 4) * Z + d];
        }
        if (b < nblk) p0 += P[b * Z + d];
        part[j][d] = p0 + p1;
        __syncthreads();

        float inv = 1.f / (float)scnt[0];
        if (tid < Z)
            s_mid[tid] = (part[0][tid] + part[1][tid]
                        + part[2][tid] + part[3][tid]) * inv;
        __syncthreads();

        // layer 1: h[j] = relu(s . W1[:,j] + b1[j])
        float acc = __ldg(b1 + tid);
#pragma unroll
        for (int dd = 0; dd < Z; dd++)
            acc = fmaf(s_mid[dd], __ldg(W1 + dd * H + tid), acc);
        h_mid[tid] = fmaxf(acc, 0.f);
        __syncthreads();

        // layer 2: D[k] = h . W2[:,k] + b2[k]
        int lane = tid & 63, grp = tid >> 6;
        float p2 = 0.f;
#pragma unroll
        for (int jj = 0; jj < 64; jj++) {
            int jidx = grp * 64 + jj;
            p2 = fmaf(h_mid[jidx], __ldg(W2 + jidx * Z + lane), p2);
        }
        __syncthreads();
        part[grp][lane] = p2;
        __syncthreads();
        if (tid < Z)
            g_D[r * Z + tid] = __ldg(b2 + tid) + part[0][tid] + part[1][tid]
                             + part[2][tid] + part[3][tid];
        __syncthreads();

        if (tid == 0) {
            __threadfence();
            atomicAdd((unsigned*)&g_ready[g], 1u);
        }
    }

    // ---------------- wait for this graph's D ----------------------------
    if (tid == 0) {
        while (g_ready[g] < (unsigned)C) __nanosleep(64);
        __threadfence();   // acquire: g_D[g]
    }
    __syncthreads();

    if (tid < C * 16)
        sD[tid] = reinterpret_cast<const float4*>(g_D)[g * C * 16 + tid];
    __syncthreads();

    // ---------------- phase 3: out = x + D[label], backward walk ----------
    {
        int lane = tid & 15;
        int grp  = tid >> 4;
        int span = n1 - n0;
        int spanA = span & ~15;

        const float4* x4 = reinterpret_cast<const float4*>(x);
        float4*       o4 = reinterpret_cast<float4*>(out);

        if (grp < (span & 15)) {
            int n = n0 + spanA + grp;
            int    c   = __ldg(label + n);
            size_t idx = ((size_t)g * N + n) * 16 + lane;
            float4 xv  = __ldg(x4 + idx);
            float4 dv  = sD[c * 16 + lane];
            float4 rv;
            rv.x = xv.x + dv.x; rv.y = xv.y + dv.y;
            rv.z = xv.z + dv.z; rv.w = xv.w + dv.w;
            __stcs(o4 + idx, rv);
        }

#pragma unroll 4
        for (int base = spanA - 16; base >= 0; base -= 16) {
            int n = n0 + base + grp;
            int    c   = __ldg(label + n);
            size_t idx = ((size_t)g * N + n) * 16 + lane;
            float4 xv  = __ldg(x4 + idx);
            float4 dv  = sD[c * 16 + lane];
            float4 rv;
            rv.x = xv.x + dv.x; rv.y = xv.y + dv.y;
            rv.z = xv.z + dv.z; rv.w = xv.w + dv.w;
            __stcs(o4 + idx, rv);
        }
    }

    // ---------------- self-reset for graph replay -------------------------
    __syncthreads();
    if (tid == 0) {
        __threadfence();
        unsigned prev = atomicAdd(&g_done[g], 1u);
        if (prev == (unsigned)(nblk - 1)) {
            g_arrive[g] = 0u;
            g_ready[g]  = 0u;
            g_done[g]   = 0u;
            __threadfence();
        }
    }
}

// ---------------------------------------------------------------- launcher
extern "C" void kernel_launch(void* const* d_in, const int* in_sizes, int n_in,
                              void* d_out, int out_size) {
    const float* x     = (const float*)d_in[0];
    const int*   label = (const int*)  d_in[1];
    const float* W1    = (const float*)d_in[2];
    const float* b1    = (const float*)d_in[3];
    const float* W2    = (const float*)d_in[4];
    const float* b2    = (const float*)d_in[5];
    float*       out   = (float*)d_out;

    int N = in_sizes[1];                 // 40000
    int G = in_sizes[0] / (N * Z);       // 16

    // Single wave: blocks = G * nblk <= 576 (< 592 slots @ 4/SM).
    int nblk = 576 / G;                  // 36 for G=16
    if (nblk > MAXBLK) nblk = MAXBLK;
    int chunk = ((N + nblk - 1) / nblk + 15) & ~15;   // multiple of 16
    nblk = (N + chunk - 1) / chunk;

    dim3 grid(nblk, G);
    fused_kernel<<<grid, 256>>>(x, label, W1, b1, W2, b2, out, N, chunk, nblk);
}

// round 9
// speedup vs baseline: 1.1224x; 1.0148x over previous
#include <cuda_runtime.h>

#define Z 64      // z_dim
#define H 256     // hidden
#define C 5       // num classes
#define GMAX 16
#define MAXBLK 64
#define T1 96     // phase-1 tile rows (= 16 groups x 6-unroll)
#define T3 96     // phase-3 tile rows

// partial class sums: layout [g][c][blk][d]
__device__ __align__(16) float g_part[GMAX * C * MAXBLK * Z];
__device__ int      g_cntp[GMAX * MAXBLK * C];   // per (g, block) class counts
__device__ __align__(16) float g_D[GMAX * C * Z];
__device__ unsigned          g_t1[GMAX];          // phase-1 tile queue
__device__ unsigned          g_t3[GMAX];          // phase-3 tile queue (reverse)
__device__ unsigned          g_arrive[GMAX];
__device__ volatile unsigned g_ready[GMAX];
__device__ unsigned          g_done[GMAX];

__device__ __forceinline__ void acc_add(float4& a, const float4& v) {
    a.x += v.x; a.y += v.y; a.z += v.z; a.w += v.w;
}

// Persistent fused kernel; per-graph decoupled sync; work-stolen tiles in the
// two memory phases. Grid (nblk, G), single wave (nblk*G <= 592 @ 4/SM —
// required for the spin loops to be deadlock-free).
__global__ void __launch_bounds__(256, 4)
fused_kernel(const float* __restrict__ x,
             const int*   __restrict__ label,
             const float* __restrict__ W1,
             const float* __restrict__ b1,
             const float* __restrict__ W2,
             const float* __restrict__ b2,
             float*       __restrict__ out,
             int N, int nblk, int nt1, int nt3) {
    int g    = blockIdx.y;
    int bx   = blockIdx.x;
    int tid  = threadIdx.x;
    int lane = tid & 15;   // float4 index within 64-dim row
    int grp  = tid >> 4;   // 16 row-groups

    __shared__ float4 sacc[16][C][16];     // 20 KB
    __shared__ float  s_mid[Z];
    __shared__ float  h_mid[H];
    __shared__ float  part[4][Z];
    __shared__ int    scnt[C];
    __shared__ int    s_tile;
    __shared__ float4 sD[C * 16];

    const float4* x4g = reinterpret_cast<const float4*>(x) + (size_t)g * N * 16;

    // ================= phase 1: class sums + counts, stolen tiles =========
    float4 acc[C];
    int    cnt[C];
#pragma unroll
    for (int c = 0; c < C; c++) { acc[c] = make_float4(0.f, 0.f, 0.f, 0.f); cnt[c] = 0; }

    if (tid == 0) s_tile = (int)atomicAdd(&g_t1[g], 1u);
    __syncthreads();
    for (;;) {
        int t = s_tile;
        if (t >= nt1) break;
        __syncthreads();                               // everyone has read t
        if (tid == 0) s_tile = (int)atomicAdd(&g_t1[g], 1u);   // claim-ahead

        int n = t * T1 + grp;
        if (t * T1 + T1 <= N) {
            // full tile: one clean 6-load burst
            int    c0 = __ldg(label + n);
            int    c1 = __ldg(label + n + 16);
            int    c2 = __ldg(label + n + 32);
            int    c3 = __ldg(label + n + 48);
            int    c4 = __ldg(label + n + 64);
            int    c5 = __ldg(label + n + 80);
            float4 v0 = __ldg(x4g + (size_t)n * 16 + lane);
            float4 v1 = __ldg(x4g + (size_t)(n + 16) * 16 + lane);
            float4 v2 = __ldg(x4g + (size_t)(n + 32) * 16 + lane);
            float4 v3 = __ldg(x4g + (size_t)(n + 48) * 16 + lane);
            float4 v4 = __ldg(x4g + (size_t)(n + 64) * 16 + lane);
            float4 v5 = __ldg(x4g + (size_t)(n + 80) * 16 + lane);
#pragma unroll
            for (int cc = 0; cc < C; cc++) {
                if (c0 == cc) acc_add(acc[cc], v0);
                if (c1 == cc) acc_add(acc[cc], v1);
                if (c2 == cc) acc_add(acc[cc], v2);
                if (c3 == cc) acc_add(acc[cc], v3);
                if (c4 == cc) acc_add(acc[cc], v4);
                if (c5 == cc) acc_add(acc[cc], v5);
                cnt[cc] += (c0 == cc) + (c1 == cc) + (c2 == cc)
                         + (c3 == cc) + (c4 == cc) + (c5 == cc);
            }
        } else {
            // last partial tile
#pragma unroll
            for (int i = 0; i < 6; i++) {
                int nn = n + 16 * i;
                if (nn < N) {
                    int    c0 = __ldg(label + nn);
                    float4 v0 = __ldg(x4g + (size_t)nn * 16 + lane);
#pragma unroll
                    for (int cc = 0; cc < C; cc++) {
                        if (c0 == cc) { acc_add(acc[cc], v0); cnt[cc]++; }
                    }
                }
            }
        }
        __syncthreads();                               // s_tile write visible
    }

    // flush: counts + partial sums into this block's static slot bx
    if (tid < C) scnt[tid] = 0;
#pragma unroll
    for (int c = 0; c < C; c++) sacc[grp][c][lane] = acc[c];
    __syncthreads();
    if (lane == 0) {
#pragma unroll
        for (int c = 0; c < C; c++)
            if (cnt[c]) atomicAdd(&scnt[c], cnt[c]);
    }
    __syncthreads();
    if (tid < C) g_cntp[(g * nblk + bx) * C + tid] = scnt[tid];
    if (tid < C * 16) {
        int c = tid >> 4, d4 = tid & 15;
        float4 s = sacc[0][c][d4];
#pragma unroll
        for (int g2 = 1; g2 < 16; g2++) {
            float4 t2 = sacc[g2][c][d4];
            s.x += t2.x; s.y += t2.y; s.z += t2.z; s.w += t2.w;
        }
        float4* P4 = reinterpret_cast<float4*>(g_part);
        P4[((size_t)(g * C + c) * nblk + bx) * 16 + d4] = s;
    }
    __syncthreads();
    if (tid == 0) {
        __threadfence();
        atomicAdd(&g_arrive[g], 1u);
    }
    __syncthreads();

    // ================= phase 2: parallel mid GEMM (blocks bx < C) =========
    if (bx < C) {
        int c = bx;
        int r = g * C + c;

        if (tid == 0) {
            while (*(volatile unsigned*)&g_arrive[g] < (unsigned)nblk)
                __nanosleep(64);
            __threadfence();   // acquire partials
        }
        __syncthreads();

        // total class count for (g, c)
        if (tid < 32) {
            int sum = 0;
            for (int b = tid; b < nblk; b += 32)
                sum += g_cntp[(g * nblk + b) * C + c];
#pragma unroll
            for (int o = 16; o > 0; o >>= 1)
                sum += __shfl_down_sync(0xffffffffu, sum, o);
            if (tid == 0) scnt[0] = max(sum, 1);
        }

        // sum partials
        const float* P = g_part + (size_t)r * nblk * Z;
        int d = tid & 63, j = tid >> 6;
        float p0 = 0.f, p1 = 0.f;
        int b = j;
        for (; b + 4 < nblk; b += 8) {
            p0 += P[b * Z + d];
            p1 += P[(b + 4) * Z + d];
        }
        if (b < nblk) p0 += P[b * Z + d];
        part[j][d] = p0 + p1;
        __syncthreads();

        float inv = 1.f / (float)scnt[0];
        if (tid < Z)
            s_mid[tid] = (part[0][tid] + part[1][tid]
                        + part[2][tid] + part[3][tid]) * inv;
        __syncthreads();

        // layer 1
        float accv = __ldg(b1 + tid);
#pragma unroll
        for (int dd = 0; dd < Z; dd++)
            accv = fmaf(s_mid[dd], __ldg(W1 + dd * H + tid), accv);
        h_mid[tid] = fmaxf(accv, 0.f);
        __syncthreads();

        // layer 2
        int lane2 = tid & 63, grp2 = tid >> 6;
        float p2 = 0.f;
#pragma unroll
        for (int jj = 0; jj < 64; jj++) {
            int jidx = grp2 * 64 + jj;
            p2 = fmaf(h_mid[jidx], __ldg(W2 + jidx * Z + lane2), p2);
        }
        __syncthreads();
        part[grp2][lane2] = p2;
        __syncthreads();
        if (tid < Z)
            g_D[r * Z + tid] = __ldg(b2 + tid) + part[0][tid] + part[1][tid]
                             + part[2][tid] + part[3][tid];
        __syncthreads();

        if (tid == 0) {
            __threadfence();
            atomicAdd((unsigned*)&g_ready[g], 1u);
        }
    }

    // ================= wait for this graph's D ============================
    if (tid == 0) {
        while (g_ready[g] < (unsigned)C) __nanosleep(64);
        __threadfence();   // acquire g_D[g]
    }
    __syncthreads();

    if (tid < C * 16)
        sD[tid] = reinterpret_cast<const float4*>(g_D)[g * C * 16 + tid];
    __syncthreads();

    // ================= phase 3: out = x + D[label], stolen reverse tiles ==
    {
        const float4* x4 = reinterpret_cast<const float4*>(x);
        float4*       o4 = reinterpret_cast<float4*>(out);

        if (tid == 0) s_tile = (int)atomicAdd(&g_t3[g], 1u);
        __syncthreads();
        for (;;) {
            int t = s_tile;
            if (t >= nt3) break;
            __syncthreads();
            if (tid == 0) s_tile = (int)atomicAdd(&g_t3[g], 1u);

            // reverse sweep: tile t covers rows [N-(t+1)*T3, N-t*T3)
            int hi = N - t * T3;
            int lo = hi - T3; if (lo < 0) lo = 0;

            if (hi - lo == T3) {
                int n = lo + grp;
                int c0 = __ldg(label + n);
                int c1 = __ldg(label + n + 16);
                int c2 = __ldg(label + n + 32);
                int c3 = __ldg(label + n + 48);
                int c4 = __ldg(label + n + 64);
                int c5 = __ldg(label + n + 80);
                size_t i0 = ((size_t)g * N + n) * 16 + lane;
                float4 v0 = __ldg(x4 + i0);
                float4 v1 = __ldg(x4 + i0 + 16 * 16);
                float4 v2 = __ldg(x4 + i0 + 32 * 16);
                float4 v3 = __ldg(x4 + i0 + 48 * 16);
                float4 v4 = __ldg(x4 + i0 + 64 * 16);
                float4 v5 = __ldg(x4 + i0 + 80 * 16);
                float4 d0 = sD[c0 * 16 + lane];
                float4 d1 = sD[c1 * 16 + lane];
                float4 d2 = sD[c2 * 16 + lane];
                float4 d3 = sD[c3 * 16 + lane];
                float4 d4 = sD[c4 * 16 + lane];
                float4 d5 = sD[c5 * 16 + lane];
                v0.x += d0.x; v0.y += d0.y; v0.z += d0.z; v0.w += d0.w;
                v1.x += d1.x; v1.y += d1.y; v1.z += d1.z; v1.w += d1.w;
                v2.x += d2.x; v2.y += d2.y; v2.z += d2.z; v2.w += d2.w;
                v3.x += d3.x; v3.y += d3.y; v3.z += d3.z; v3.w += d3.w;
                v4.x += d4.x; v4.y += d4.y; v4.z += d4.z; v4.w += d4.w;
                v5.x += d5.x; v5.y += d5.y; v5.z += d5.z; v5.w += d5.w;
                __stcs(o4 + i0,           v0);
                __stcs(o4 + i0 + 16 * 16, v1);
                __stcs(o4 + i0 + 32 * 16, v2);
                __stcs(o4 + i0 + 48 * 16, v3);
                __stcs(o4 + i0 + 64 * 16, v4);
                __stcs(o4 + i0 + 80 * 16, v5);
            } else {
                for (int n = lo + grp; n < hi; n += 16) {
                    int    c   = __ldg(label + n);
                    size_t idx = ((size_t)g * N + n) * 16 + lane;
                    float4 xv  = __ldg(x4 + idx);
                    float4 dv  = sD[c * 16 + lane];
                    xv.x += dv.x; xv.y += dv.y; xv.z += dv.z; xv.w += dv.w;
                    __stcs(o4 + idx, xv);
                }
            }
            __syncthreads();
        }
    }

    // ================= self-reset for graph replay ========================
    __syncthreads();
    if (tid == 0) {
        __threadfence();
        unsigned prev = atomicAdd(&g_done[g], 1u);
        if (prev == (unsigned)(nblk - 1)) {
            g_t1[g]     = 0u;
            g_t3[g]     = 0u;
            g_arrive[g] = 0u;
            g_ready[g]  = 0u;
            g_done[g]   = 0u;
            __threadfence();
        }
    }
}

// ---------------------------------------------------------------- launcher
extern "C" void kernel_launch(void* const* d_in, const int* in_sizes, int n_in,
                              void* d_out, int out_size) {
    const float* x     = (const float*)d_in[0];
    const int*   label = (const int*)  d_in[1];
    const float* W1    = (const float*)d_in[2];
    const float* b1    = (const float*)d_in[3];
    const float* W2    = (const float*)d_in[4];
    const float* b2    = (const float*)d_in[5];
    float*       out   = (float*)d_out;

    int N = in_sizes[1];                 // 40000
    int G = in_sizes[0] / (N * Z);       // 16

    // Single wave: blocks = G * nblk <= 576 (< 592 slots @ 4/SM).
    int nblk = 576 / G;                  // 36 for G=16
    if (nblk > MAXBLK) nblk = MAXBLK;
    if (nblk < C + 1) nblk = C + 1;      // need >= C blocks per graph for mid

    int nt1 = (N + T1 - 1) / T1;
    int nt3 = (N + T3 - 1) / T3;

    dim3 grid(nblk, G);
    fused_kernel<<<grid, 256>>>(x, label, W1, b1, W2, b2, out,
                                N, nblk, nt1, nt3);
}